// round 5
// baseline (speedup 1.0000x reference)
#include <cuda_runtime.h>
#include <cuda_bf16.h>
#include <cstdint>

#define N_WORDS 30000
#define EMB_DIM 784
#define MAT_DIM 28
#define BATCH   1024
#define SEQ     64

// 4 warps per block, one block per sequence. Each warp owns a 16-token chunk.
#define WARPS_PER_BLOCK 4
#define CHUNK 16
#define THREADS (WARPS_PER_BLOCK * 32)

// ---------------------------------------------------------------------------
// f32x2 packed-FMA helpers (FFMA2 is only reachable via PTX fma.rn.f32x2)
// ---------------------------------------------------------------------------
__device__ __forceinline__ unsigned long long pack2(float x, float y) {
    unsigned long long r;
    asm("mov.b64 %0, {%1, %2};" : "=l"(r) : "f"(x), "f"(y));
    return r;
}
__device__ __forceinline__ void unpack2(unsigned long long d, float& x, float& y) {
    asm("mov.b64 {%0, %1}, %2;" : "=f"(x), "=f"(y) : "l"(d));
}
__device__ __forceinline__ void fma2(unsigned long long& d,
                                     unsigned long long a,
                                     unsigned long long b) {
    asm("fma.rn.f32x2 %0, %1, %2, %0;" : "+l"(d) : "l"(a), "l"(b));
}
__device__ __forceinline__ unsigned long long mul2(unsigned long long a,
                                                   unsigned long long b) {
    unsigned long long d;
    asm("mul.rn.f32x2 %0, %1, %2;" : "=l"(d) : "l"(a), "l"(b));
    return d;
}

// cp.async 16B global -> shared
__device__ __forceinline__ void cp16(void* s, const void* g) {
    unsigned saddr = (unsigned)__cvta_generic_to_shared(s);
    asm volatile("cp.async.cg.shared.global [%0], [%1], 16;\n"
                 :: "r"(saddr), "l"(g) : "memory");
}
__device__ __forceinline__ void cp_commit() {
    asm volatile("cp.async.commit_group;\n" ::: "memory");
}
__device__ __forceinline__ void cp_wait1() {   // allow 1 group in flight
    asm volatile("cp.async.wait_group 1;\n" ::: "memory");
}
__device__ __forceinline__ void cp_wait0() {
    asm volatile("cp.async.wait_group 0;\n" ::: "memory");
}

// ---------------------------------------------------------------------------
// cur(row r, registers of lane r) = cur @ M, M (28x28 row-major) in shared.
// All lanes read identical M addresses -> LDS.128 broadcast (N=1, conflict
// free). 14 mul2 + 378 fma2 + 196 LDS.128 per call.
// ---------------------------------------------------------------------------
__device__ __forceinline__ void matmul28(float cur[MAT_DIM], const float* sM) {
    unsigned long long acc[14];

    // k = 0: initialize accumulators with a multiply (no zero-init pass)
    {
        unsigned long long a2 = pack2(cur[0], cur[0]);
        const ulonglong2* row = reinterpret_cast<const ulonglong2*>(sM);
#pragma unroll
        for (int j = 0; j < 7; ++j) {
            ulonglong2 b = row[j];
            acc[2 * j]     = mul2(a2, b.x);
            acc[2 * j + 1] = mul2(a2, b.y);
        }
    }
#pragma unroll
    for (int k = 1; k < MAT_DIM; ++k) {
        unsigned long long a2 = pack2(cur[k], cur[k]);
        const ulonglong2* row = reinterpret_cast<const ulonglong2*>(sM + k * MAT_DIM);
#pragma unroll
        for (int j = 0; j < 7; ++j) {
            ulonglong2 b = row[j];                 // LDS.128 broadcast
            fma2(acc[2 * j],     a2, b.x);
            fma2(acc[2 * j + 1], a2, b.y);
        }
    }
#pragma unroll
    for (int j = 0; j < 14; ++j) unpack2(acc[j], cur[2 * j], cur[2 * j + 1]);
}

__device__ __forceinline__ void store_row_shared(float* dst, const float cur[MAT_DIM]) {
    float4* o = reinterpret_cast<float4*>(dst);
#pragma unroll
    for (int j = 0; j < 7; ++j)
        o[j] = make_float4(cur[4 * j], cur[4 * j + 1], cur[4 * j + 2], cur[4 * j + 3]);
}

__global__ void __launch_bounds__(THREADS)
w2m_kernel(const int* __restrict__ sent,
           const float* __restrict__ table,
           float* __restrict__ out) {
    // Double-buffered right-operand per warp; buffers are reused as the
    // combine scratch after the main loop (no separate comb array -> 25 KB).
    __shared__ __align__(16) float mbuf[WARPS_PER_BLOCK][2][EMB_DIM];

    const int seq  = blockIdx.x;
    const int w    = threadIdx.x >> 5;
    const int lane = threadIdx.x & 31;
    const bool active = (lane < MAT_DIM);
    const int r = lane;

    // Lane t (<16) holds token index t of this warp's chunk.
    int sidx = 0;
    if (lane < CHUNK) sidx = sent[(size_t)seq * SEQ + w * CHUNK + lane];

    float cur[MAT_DIM];

    // Prefetch token 0.
    {
        int idx0 = __shfl_sync(0xffffffffu, sidx, 0);
        const float* src = table + (size_t)idx0 * EMB_DIM;
        float* dst = mbuf[w][0];
#pragma unroll
        for (int i = 0; i < EMB_DIM / 4; i += 32) {
            int e = i + lane;
            if (e < EMB_DIM / 4) cp16(dst + e * 4, src + e * 4);
        }
        cp_commit();
    }

#pragma unroll 1
    for (int t = 0; t < CHUNK; ++t) {
        // Issue prefetch for t+1 FIRST, then wait with 1 group allowed in
        // flight: guarantees token t's data has landed while t+1 streams in
        // behind the full matmul.
        if (t < CHUNK - 1) {
            int idx = __shfl_sync(0xffffffffu, sidx, t + 1);
            const float* src = table + (size_t)idx * EMB_DIM;
            float* dst = mbuf[w][(t + 1) & 1];
#pragma unroll
            for (int i = 0; i < EMB_DIM / 4; i += 32) {
                int e = i + lane;
                if (e < EMB_DIM / 4) cp16(dst + e * 4, src + e * 4);
            }
            cp_commit();
            cp_wait1();
        } else {
            cp_wait0();
        }
        __syncwarp();

        if (active) {
            if (t == 0) {
                const float4* rowp =
                    reinterpret_cast<const float4*>(&mbuf[w][0][r * MAT_DIM]);
#pragma unroll
                for (int j = 0; j < 7; ++j) {
                    float4 v = rowp[j];
                    cur[4 * j] = v.x; cur[4 * j + 1] = v.y;
                    cur[4 * j + 2] = v.z; cur[4 * j + 3] = v.w;
                }
            } else {
                matmul28(cur, mbuf[w][t & 1]);
            }
        }
    }

    // ---- Combine (reuse mbuf[w][0] as scratch) ----
    // Publish odd-warp partials P1, P3.
    if (active && (w == 1 || w == 3)) store_row_shared(&mbuf[w][0][r * MAT_DIM], cur);
    __syncthreads();

    // warp0: P0@P1 ; warp2: P2@P3 (store to mbuf[2][0])
    if (active && (w == 0 || w == 2)) matmul28(cur, mbuf[w + 1][0]);
    if (active && w == 2) store_row_shared(&mbuf[2][0][r * MAT_DIM], cur);
    __syncthreads();

    // warp0: (P0@P1) @ (P2@P3) -> out
    if (active && w == 0) {
        matmul28(cur, mbuf[2][0]);
        float4* o = reinterpret_cast<float4*>(out + (size_t)seq * EMB_DIM + r * MAT_DIM);
#pragma unroll
        for (int j = 0; j < 7; ++j)
            o[j] = make_float4(cur[4 * j], cur[4 * j + 1], cur[4 * j + 2], cur[4 * j + 3]);
    }
}

extern "C" void kernel_launch(void* const* d_in, const int* in_sizes, int n_in,
                              void* d_out, int out_size) {
    const int* sent;
    const float* table;
    if (in_sizes[0] == BATCH * SEQ) {
        sent  = (const int*)d_in[0];
        table = (const float*)d_in[1];
    } else {
        sent  = (const int*)d_in[1];
        table = (const float*)d_in[0];
    }
    float* out = (float*)d_out;
    (void)n_in; (void)out_size;

    w2m_kernel<<<BATCH, THREADS>>>(sent, table, out);
}

// round 10
// speedup vs baseline: 1.1064x; 1.1064x over previous
#include <cuda_runtime.h>
#include <cuda_bf16.h>
#include <cstdint>

#define N_WORDS 30000
#define EMB_DIM 784
#define MAT_DIM 28
#define BATCH   1024
#define SEQ     64

// 4 warps per block, one block per sequence, each warp owns a 16-token chunk.
// __launch_bounds__(128, 7): 7 blocks/SM -> 148*7 = 1036 >= 1024 blocks ->
// EXACTLY ONE WAVE (R3/R5 ran 1.15-1.4 waves; uniform T_CTA made the partial
// second wave cost nearly a full extra block time).
#define WARPS_PER_BLOCK 4
#define CHUNK 16
#define THREADS (WARPS_PER_BLOCK * 32)
#define MIN_BLOCKS_PER_SM 7

// ---------------------------------------------------------------------------
// f32x2 packed-FMA helpers (FFMA2 only reachable via PTX fma.rn.f32x2)
// ---------------------------------------------------------------------------
__device__ __forceinline__ unsigned long long pack2(float x, float y) {
    unsigned long long r;
    asm("mov.b64 %0, {%1, %2};" : "=l"(r) : "f"(x), "f"(y));
    return r;
}
__device__ __forceinline__ void unpack2(unsigned long long d, float& x, float& y) {
    asm("mov.b64 {%0, %1}, %2;" : "=f"(x), "=f"(y) : "l"(d));
}
__device__ __forceinline__ void fma2(unsigned long long& d,
                                     unsigned long long a,
                                     unsigned long long b) {
    asm("fma.rn.f32x2 %0, %1, %2, %0;" : "+l"(d) : "l"(a), "l"(b));
}
__device__ __forceinline__ unsigned long long mul2(unsigned long long a,
                                                   unsigned long long b) {
    unsigned long long d;
    asm("mul.rn.f32x2 %0, %1, %2;" : "=l"(d) : "l"(a), "l"(b));
    return d;
}

// cp.async 16B global -> shared
__device__ __forceinline__ void cp16(void* s, const void* g) {
    unsigned saddr = (unsigned)__cvta_generic_to_shared(s);
    asm volatile("cp.async.cg.shared.global [%0], [%1], 16;\n"
                 :: "r"(saddr), "l"(g) : "memory");
}
__device__ __forceinline__ void cp_commit() {
    asm volatile("cp.async.commit_group;\n" ::: "memory");
}
__device__ __forceinline__ void cp_wait0() {
    asm volatile("cp.async.wait_group 0;\n" ::: "memory");
}

// Warp-cooperative prefetch of one 28x28 fp32 matrix.
// 784 floats = 3136 bytes = 196 x 16B chunks (NOT 49 — R9's bug).
// Lane l copies chunks l, l+32, ..., l+192: 6 full rounds, lanes 0..3 a 7th.
__device__ __forceinline__ void prefetch_mat(float* dst, const float* src, int lane) {
#pragma unroll
    for (int i = 0; i < 7; ++i) {
        int e = lane + i * 32;
        if (e < EMB_DIM / 4) cp16(dst + e * 4, src + e * 4);
    }
    cp_commit();
}

// ---------------------------------------------------------------------------
// cur(row r, registers of lane r) = cur @ M, M (28x28 row-major) in shared.
// All lanes read identical M addresses -> LDS.128 broadcast (conflict-free).
// 14 mul2 + 378 fma2 + 196 LDS.128 per call.
// ---------------------------------------------------------------------------
__device__ __forceinline__ void matmul28(float cur[MAT_DIM], const float* sM) {
    unsigned long long acc[14];

    {   // k = 0: init accumulators with multiply (no zero-init pass)
        unsigned long long a2 = pack2(cur[0], cur[0]);
        const ulonglong2* row = reinterpret_cast<const ulonglong2*>(sM);
#pragma unroll
        for (int j = 0; j < 7; ++j) {
            ulonglong2 b = row[j];
            acc[2 * j]     = mul2(a2, b.x);
            acc[2 * j + 1] = mul2(a2, b.y);
        }
    }
#pragma unroll
    for (int k = 1; k < MAT_DIM; ++k) {
        unsigned long long a2 = pack2(cur[k], cur[k]);
        const ulonglong2* row = reinterpret_cast<const ulonglong2*>(sM + k * MAT_DIM);
#pragma unroll
        for (int j = 0; j < 7; ++j) {
            ulonglong2 b = row[j];                 // LDS.128 broadcast
            fma2(acc[2 * j],     a2, b.x);
            fma2(acc[2 * j + 1], a2, b.y);
        }
    }
#pragma unroll
    for (int j = 0; j < 14; ++j) unpack2(acc[j], cur[2 * j], cur[2 * j + 1]);
}

__device__ __forceinline__ void store_row_shared(float* dst, const float cur[MAT_DIM]) {
    float4* o = reinterpret_cast<float4*>(dst);
#pragma unroll
    for (int j = 0; j < 7; ++j)
        o[j] = make_float4(cur[4 * j], cur[4 * j + 1], cur[4 * j + 2], cur[4 * j + 3]);
}

__global__ void __launch_bounds__(THREADS, MIN_BLOCKS_PER_SM)
w2m_kernel(const int* __restrict__ sent,
           const float* __restrict__ table,
           float* __restrict__ out) {
    // Double-buffered right operand per warp; reused as combine scratch. 25 KB.
    __shared__ __align__(16) float mbuf[WARPS_PER_BLOCK][2][EMB_DIM];

    const int seq  = blockIdx.x;
    const int w    = threadIdx.x >> 5;
    const int lane = threadIdx.x & 31;
    const bool active = (lane < MAT_DIM);
    const int r = lane;

    // Lane t (<16) holds token index t of this warp's chunk.
    int sidx = 0;
    if (lane < CHUNK) sidx = sent[(size_t)seq * SEQ + w * CHUNK + lane];

    float cur[MAT_DIM];

    // Prefetch token 0.
    {
        int idx0 = __shfl_sync(0xffffffffu, sidx, 0);
        prefetch_mat(mbuf[w][0], table + (size_t)idx0 * EMB_DIM, lane);
    }

#pragma unroll 1
    for (int t = 0; t < CHUNK; ++t) {
        cp_wait0();           // token t landed
        __syncwarp();
        if (t < CHUNK - 1) {  // stream token t+1 behind the matmul below
            int idx = __shfl_sync(0xffffffffu, sidx, t + 1);
            prefetch_mat(mbuf[w][(t + 1) & 1], table + (size_t)idx * EMB_DIM, lane);
        }
        if (active) {
            if (t == 0) {
                const float4* rowp =
                    reinterpret_cast<const float4*>(&mbuf[w][0][r * MAT_DIM]);
#pragma unroll
                for (int j = 0; j < 7; ++j) {
                    float4 v = rowp[j];
                    cur[4 * j] = v.x; cur[4 * j + 1] = v.y;
                    cur[4 * j + 2] = v.z; cur[4 * j + 3] = v.w;
                }
            } else {
                matmul28(cur, mbuf[w][t & 1]);
            }
        }
    }

    // ---- Combine (reuse mbuf as scratch) ----
    if (active && (w == 1 || w == 3)) store_row_shared(&mbuf[w][0][r * MAT_DIM], cur);
    __syncthreads();

    if (active && (w == 0 || w == 2)) matmul28(cur, mbuf[w + 1][0]);   // P0@P1, P2@P3
    if (active && w == 2) store_row_shared(&mbuf[2][0][r * MAT_DIM], cur);
    __syncthreads();

    if (active && w == 0) {                                            // final
        matmul28(cur, mbuf[2][0]);
        float4* o = reinterpret_cast<float4*>(out + (size_t)seq * EMB_DIM + r * MAT_DIM);
#pragma unroll
        for (int j = 0; j < 7; ++j)
            o[j] = make_float4(cur[4 * j], cur[4 * j + 1], cur[4 * j + 2], cur[4 * j + 3]);
    }
}

extern "C" void kernel_launch(void* const* d_in, const int* in_sizes, int n_in,
                              void* d_out, int out_size) {
    const int* sent;
    const float* table;
    if (in_sizes[0] == BATCH * SEQ) {
        sent  = (const int*)d_in[0];
        table = (const float*)d_in[1];
    } else {
        sent  = (const int*)d_in[1];
        table = (const float*)d_in[0];
    }
    float* out = (float*)d_out;
    (void)n_in; (void)out_size;

    w2m_kernel<<<BATCH, THREADS>>>(sent, table, out);
}